// round 12
// baseline (speedup 1.0000x reference)
#include <cuda_runtime.h>
#include <cuda_fp16.h>
#include <cstdint>

// BinarizedLinear: out[M,N] = x[M,K] @ sign(W)[N,K]^T + bias[N]
// M=8192, N=4096, K=4096, fp32 in/out.
//
// sm_103 (non-'a') PTX target -> no tcgen05; legacy mma.sync path.
// fp16 data (sign(W) exact; x rounded -> rel_err ~2e-4, fp32 accum).
// Round 10: R8 topology (128x128x64 tile, 8 warps 2x4, 3 stages, 96KB smem,
// 2 CTAs/SM = 16 warps/SM) + cp.async issues interleaved into the ks compute
// blocks so LSU/MIO pressure lands in the ldmatrix->HMMA shadow instead of a
// burst at stage start (R9 proved the loop is tensor-pipe bound, not
// crossbar bound; the remaining slack is issue/dependency bubbles).

#define M_DIM 8192
#define N_DIM 4096
#define K_DIM 4096

#define BM 128
#define BN 128
#define BK 64
#define STAGES 3
#define KTILES (K_DIM / BK)   // 64
#define NTHREADS 256

// fp16 scratch (allocation-free: __device__ globals)
__device__ __half g_A[(size_t)M_DIM * K_DIM];   // 64 MB
__device__ __half g_B[(size_t)N_DIM * K_DIM];   // 32 MB

// ---------------------------------------------------------------------------
// Conversion kernels
// ---------------------------------------------------------------------------

__global__ void convert_x_kernel(const float* __restrict__ x) {
    const size_t n4 = (size_t)M_DIM * K_DIM / 4;
    const float4* in = (const float4*)x;
    uint2* out = (uint2*)g_A;
    for (size_t i = (size_t)blockIdx.x * blockDim.x + threadIdx.x; i < n4;
         i += (size_t)gridDim.x * blockDim.x) {
        float4 v = in[i];
        __half2 h0 = __floats2half2_rn(v.x, v.y);
        __half2 h1 = __floats2half2_rn(v.z, v.w);
        uint2 o;
        o.x = *reinterpret_cast<uint32_t*>(&h0);
        o.y = *reinterpret_cast<uint32_t*>(&h1);
        out[i] = o;
    }
}

__device__ __forceinline__ float signf_strict(float v) {
    return (v > 0.0f) ? 1.0f : ((v < 0.0f) ? -1.0f : 0.0f);
}

__global__ void convert_w_kernel(const float* __restrict__ w) {
    const size_t n4 = (size_t)N_DIM * K_DIM / 4;
    const float4* in = (const float4*)w;
    uint2* out = (uint2*)g_B;
    for (size_t i = (size_t)blockIdx.x * blockDim.x + threadIdx.x; i < n4;
         i += (size_t)gridDim.x * blockDim.x) {
        float4 v = in[i];
        __half2 h0 = __floats2half2_rn(signf_strict(v.x), signf_strict(v.y));
        __half2 h1 = __floats2half2_rn(signf_strict(v.z), signf_strict(v.w));
        uint2 o;
        o.x = *reinterpret_cast<uint32_t*>(&h0);
        o.y = *reinterpret_cast<uint32_t*>(&h1);
        out[i] = o;
    }
}

// ---------------------------------------------------------------------------
// GEMM kernel
// ---------------------------------------------------------------------------
// CTA tile: 128(M) x 128(N) x 64(K). 256 threads = 8 warps in 2(M) x 4(N).
// Warp tile: 64 x 32 -> 4(m16) x 4(n8) = 16 mma.m16n8k16 per k16 step.
// SMEM: rows of 64 halves = 128 bytes; SW128 swizzle (seg ^= row&7).
// 3 stages x 32KB = 96KB -> 2 CTAs/SM.

#define A_STAGE_BYTES (BM * 128)              // 16 KB
#define B_STAGE_BYTES (BN * 128)              // 16 KB
#define STAGE_BYTES   (A_STAGE_BYTES + B_STAGE_BYTES)  // 32 KB
#define SMEM_BYTES    (STAGES * STAGE_BYTES)  // 96 KB

__global__ void __launch_bounds__(NTHREADS, 2)
binlinear_gemm_kernel(const float* __restrict__ bias, float* __restrict__ out) {
    extern __shared__ char smem[];
    uint32_t smem_u32;
    asm("{ .reg .u64 t; cvta.to.shared.u64 t, %1; cvt.u32.u64 %0, t; }"
        : "=r"(smem_u32) : "l"(smem));

    const int tid  = threadIdx.x;
    const int lane = tid & 31;
    const int wid  = tid >> 5;
    const int warp_m = (wid >> 2) * 64;   // 0 or 64
    const int warp_n = (wid & 3) * 32;    // 0,32,64,96

    const int m0 = blockIdx.y * BM;
    const int n0 = blockIdx.x * BN;

    // Per-thread cp.async source/dst precompute: each thread owns 4 A-chunks
    // and 4 B-chunks per stage (chunk i: cid = tid + i*256).
    // cid -> row = cid>>3, seg = cid&7; dst = row*128 + ((seg^(row&7))<<4).
    uint32_t a_dst_off[4], b_dst_off[4];
    const __half* a_src[4];
    const __half* b_src[4];
#pragma unroll
    for (int i = 0; i < 4; ++i) {
        int cid = tid + i * NTHREADS;
        int row = cid >> 3, seg = cid & 7;
        uint32_t off = (uint32_t)row * 128 + ((seg ^ (row & 7)) << 4);
        a_dst_off[i] = off;
        b_dst_off[i] = off;
        a_src[i] = g_A + (size_t)(m0 + row) * K_DIM + seg * 8;
        b_src[i] = g_B + (size_t)(n0 + row) * K_DIM + seg * 8;
    }

    // Issue A-chunk i and B-chunk i for stage s, k-tile kt.
    auto load_chunk = [&](int s, int kt, int i) {
        const uint32_t a_base = smem_u32 + s * STAGE_BYTES;
        const uint32_t b_base = a_base + A_STAGE_BYTES;
        const __half* sa = a_src[i] + kt * BK;
        const __half* sb = b_src[i] + kt * BK;
        asm volatile("cp.async.cg.shared.global [%0], [%1], 16;\n"
                     :: "r"(a_base + a_dst_off[i]), "l"(sa));
        asm volatile("cp.async.cg.shared.global [%0], [%1], 16;\n"
                     :: "r"(b_base + b_dst_off[i]), "l"(sb));
    };

    // ---- ldmatrix lane addressing -----------------------------------------
    // A (no trans), x4 -> (m0-7,klo),(m8-15,klo),(m0-7,khi),(m8-15,khi)
    const int a_g  = lane >> 3;
    const int a_row_in = (lane & 7) + (a_g & 1) * 8;
    const int a_hi = a_g >> 1;                 // +8 halves in k
    // B (no trans; smem [n][k] k-contiguous = mma B layout),
    // x4 -> (n0-7,klo),(n0-7,khi),(n8-15,klo),(n8-15,khi)
    const int b_row_in = (lane & 7) + ((a_g >> 1) & 1) * 8;
    const int b_hi = a_g & 1;
    const int sxor = lane & 7;

    uint32_t a_row_off[4];
#pragma unroll
    for (int mi = 0; mi < 4; ++mi)
        a_row_off[mi] = (uint32_t)(warp_m + mi * 16 + a_row_in) * 128;
    uint32_t b_row_off[2];
#pragma unroll
    for (int nj = 0; nj < 2; ++nj)
        b_row_off[nj] = (uint32_t)(warp_n + nj * 16 + b_row_in) * 128;

    float acc[4][4][4];
#pragma unroll
    for (int mi = 0; mi < 4; ++mi)
#pragma unroll
        for (int nk = 0; nk < 4; ++nk)
#pragma unroll
            for (int r = 0; r < 4; ++r) acc[mi][nk][r] = 0.0f;

    // ---- prologue: preload 2 stages ---------------------------------------
#pragma unroll
    for (int s = 0; s < STAGES - 1; ++s) {
#pragma unroll
        for (int i = 0; i < 4; ++i) load_chunk(s, s, i);
        asm volatile("cp.async.commit_group;\n");
    }

    // ---- mainloop ----------------------------------------------------------
    int stage = 0;
    for (int kt = 0; kt < KTILES; ++kt) {
        asm volatile("cp.async.wait_group %0;\n" :: "n"(STAGES - 2));
        __syncthreads();

        const int ld = kt + STAGES - 1;
        const bool do_load = (ld < KTILES);
        int lds = stage + (STAGES - 1);
        if (lds >= STAGES) lds -= STAGES;

        const uint32_t a_base = smem_u32 + stage * STAGE_BYTES;
        const uint32_t b_base = a_base + A_STAGE_BYTES;
        if (++stage == STAGES) stage = 0;

#pragma unroll
        for (int ks = 0; ks < 4; ++ks) {
            uint32_t af[4][4];
            uint32_t bf[2][4];
#pragma unroll
            for (int mi = 0; mi < 4; ++mi) {
                uint32_t addr = a_base + a_row_off[mi]
                              + ((uint32_t)((ks * 2 + a_hi) ^ sxor) << 4);
                asm volatile(
                    "ldmatrix.sync.aligned.m8n8.x4.shared.b16 {%0,%1,%2,%3}, [%4];\n"
                    : "=r"(af[mi][0]), "=r"(af[mi][1]),
                      "=r"(af[mi][2]), "=r"(af[mi][3])
                    : "r"(addr));
            }
#pragma unroll
            for (int nj = 0; nj < 2; ++nj) {
                uint32_t addr = b_base + b_row_off[nj]
                              + ((uint32_t)((ks * 2 + b_hi) ^ sxor) << 4);
                asm volatile(
                    "ldmatrix.sync.aligned.m8n8.x4.shared.b16 {%0,%1,%2,%3}, [%4];\n"
                    : "=r"(bf[nj][0]), "=r"(bf[nj][1]),
                      "=r"(bf[nj][2]), "=r"(bf[nj][3])
                    : "r"(addr));
            }

            // Interleaved next-stage load: one A+B chunk pair per ks block,
            // issued in the ldmatrix->HMMA dependency shadow.
            if (do_load) load_chunk(lds, ld, ks);

#pragma unroll
            for (int mi = 0; mi < 4; ++mi) {
#pragma unroll
                for (int nk = 0; nk < 4; ++nk) {
                    const int nj = nk >> 1;
                    const int sub = (nk & 1) * 2;
                    asm volatile(
                        "mma.sync.aligned.m16n8k16.row.col.f32.f16.f16.f32 "
                        "{%0,%1,%2,%3}, {%4,%5,%6,%7}, {%8,%9}, {%0,%1,%2,%3};\n"
                        : "+f"(acc[mi][nk][0]), "+f"(acc[mi][nk][1]),
                          "+f"(acc[mi][nk][2]), "+f"(acc[mi][nk][3])
                        : "r"(af[mi][0]), "r"(af[mi][1]),
                          "r"(af[mi][2]), "r"(af[mi][3]),
                          "r"(bf[nj][sub]), "r"(bf[nj][sub + 1]));
                }
            }
        }
        asm volatile("cp.async.commit_group;\n");
    }

    // ---- epilogue: bias + fp32 store --------------------------------------
    float bcol[4][2];
#pragma unroll
    for (int nk = 0; nk < 4; ++nk) {
        const int c = n0 + warp_n + nk * 8 + (lane & 3) * 2;
        bcol[nk][0] = bias[c];
        bcol[nk][1] = bias[c + 1];
    }
#pragma unroll
    for (int mi = 0; mi < 4; ++mi) {
        const int r0 = m0 + warp_m + mi * 16 + (lane >> 2);
#pragma unroll
        for (int nk = 0; nk < 4; ++nk) {
            const int c = n0 + warp_n + nk * 8 + (lane & 3) * 2;
            float2 v;
            v.x = acc[mi][nk][0] + bcol[nk][0];
            v.y = acc[mi][nk][1] + bcol[nk][1];
            *reinterpret_cast<float2*>(&out[(size_t)r0 * N_DIM + c]) = v;
            v.x = acc[mi][nk][2] + bcol[nk][0];
            v.y = acc[mi][nk][3] + bcol[nk][1];
            *reinterpret_cast<float2*>(&out[(size_t)(r0 + 8) * N_DIM + c]) = v;
        }
    }
}

// ---------------------------------------------------------------------------
// Launch
// ---------------------------------------------------------------------------

extern "C" void kernel_launch(void* const* d_in, const int* in_sizes, int n_in,
                              void* d_out, int out_size) {
    const float* x    = (const float*)d_in[0];
    const float* w    = (const float*)d_in[1];
    const float* bias = (const float*)d_in[2];
    float* out        = (float*)d_out;

    convert_x_kernel<<<2048, 256>>>(x);
    convert_w_kernel<<<2048, 256>>>(w);

    cudaFuncSetAttribute(binlinear_gemm_kernel,
                         cudaFuncAttributeMaxDynamicSharedMemorySize,
                         SMEM_BYTES);

    dim3 grid(N_DIM / BN, M_DIM / BM);   // (32, 64)
    binlinear_gemm_kernel<<<grid, NTHREADS, SMEM_BYTES>>>(bias, out);
}

// round 13
// speedup vs baseline: 1.6764x; 1.6764x over previous
#include <cuda_runtime.h>
#include <cuda_fp16.h>
#include <cstdint>

// BinarizedLinear: out[M,N] = x[M,K] @ sign(W)[N,K]^T + bias[N]
// M=8192, N=4096, K=4096, fp32 in/out.
//
// sm_103 (non-'a') PTX target -> no tcgen05; legacy mma.sync path.
// fp16 data (sign(W) exact; x rounded -> rel_err ~2e-4, fp32 accum).
//
// Round 13 = R8 (best, 651us) with two minimal deltas:
//  (1) load burst moved after the ks=0 compute block, commit IMMEDIATELY
//      after the burst (same group-per-iteration accounting as R8 -> same
//      pipeline depth; R12 regression was caused by commit at end-of-stage).
//  (2) both conversion passes merged into one grid-stride kernel.

#define M_DIM 8192
#define N_DIM 4096
#define K_DIM 4096

#define BM 128
#define BN 128
#define BK 64
#define STAGES 3
#define KTILES (K_DIM / BK)   // 64
#define NTHREADS 256

// fp16 scratch (allocation-free: __device__ globals)
__device__ __half g_A[(size_t)M_DIM * K_DIM];   // 64 MB
__device__ __half g_B[(size_t)N_DIM * K_DIM];   // 32 MB

// ---------------------------------------------------------------------------
// Merged conversion kernel: x -> fp16 (g_A), sign(w) -> fp16 (g_B)
// ---------------------------------------------------------------------------

__device__ __forceinline__ float signf_strict(float v) {
    return (v > 0.0f) ? 1.0f : ((v < 0.0f) ? -1.0f : 0.0f);
}

__global__ void convert_both_kernel(const float* __restrict__ x,
                                    const float* __restrict__ w) {
    const size_t n4x = (size_t)M_DIM * K_DIM / 4;   // 8,388,608
    const size_t n4w = (size_t)N_DIM * K_DIM / 4;   // 4,194,304
    const size_t total = n4x + n4w;
    const float4* inx = (const float4*)x;
    const float4* inw = (const float4*)w;
    uint2* outa = (uint2*)g_A;
    uint2* outb = (uint2*)g_B;
    for (size_t i = (size_t)blockIdx.x * blockDim.x + threadIdx.x; i < total;
         i += (size_t)gridDim.x * blockDim.x) {
        if (i < n4x) {
            float4 v = inx[i];
            __half2 h0 = __floats2half2_rn(v.x, v.y);
            __half2 h1 = __floats2half2_rn(v.z, v.w);
            uint2 o;
            o.x = *reinterpret_cast<uint32_t*>(&h0);
            o.y = *reinterpret_cast<uint32_t*>(&h1);
            outa[i] = o;
        } else {
            size_t j = i - n4x;
            float4 v = inw[j];
            __half2 h0 = __floats2half2_rn(signf_strict(v.x), signf_strict(v.y));
            __half2 h1 = __floats2half2_rn(signf_strict(v.z), signf_strict(v.w));
            uint2 o;
            o.x = *reinterpret_cast<uint32_t*>(&h0);
            o.y = *reinterpret_cast<uint32_t*>(&h1);
            outb[j] = o;
        }
    }
}

// ---------------------------------------------------------------------------
// GEMM kernel
// ---------------------------------------------------------------------------
// CTA tile: 128(M) x 128(N) x 64(K). 256 threads = 8 warps in 2(M) x 4(N).
// Warp tile: 64 x 32 -> 4(m16) x 4(n8) = 16 mma.m16n8k16 per k16 step.
// SMEM: rows of 64 halves = 128 bytes; SW128 swizzle (seg ^= row&7).
// 3 stages x 32KB = 96KB -> 2 CTAs/SM.

#define A_STAGE_BYTES (BM * 128)              // 16 KB
#define B_STAGE_BYTES (BN * 128)              // 16 KB
#define STAGE_BYTES   (A_STAGE_BYTES + B_STAGE_BYTES)  // 32 KB
#define SMEM_BYTES    (STAGES * STAGE_BYTES)  // 96 KB

__global__ void __launch_bounds__(NTHREADS, 2)
binlinear_gemm_kernel(const float* __restrict__ bias, float* __restrict__ out) {
    extern __shared__ char smem[];
    uint32_t smem_u32;
    asm("{ .reg .u64 t; cvta.to.shared.u64 t, %1; cvt.u32.u64 %0, t; }"
        : "=r"(smem_u32) : "l"(smem));

    const int tid  = threadIdx.x;
    const int lane = tid & 31;
    const int wid  = tid >> 5;
    const int warp_m = (wid >> 2) * 64;   // 0 or 64
    const int warp_n = (wid & 3) * 32;    // 0,32,64,96

    const int m0 = blockIdx.y * BM;
    const int n0 = blockIdx.x * BN;

    // ---- cp.async stage loader (monolithic burst, as in R8) ---------------
    auto load_stage = [&](int s, int kt) {
        const uint32_t a_base = smem_u32 + s * STAGE_BYTES;
        const uint32_t b_base = a_base + A_STAGE_BYTES;
        const __half* gA = g_A + (size_t)m0 * K_DIM + kt * BK;
        const __half* gB = g_B + (size_t)n0 * K_DIM + kt * BK;
#pragma unroll
        for (int i = 0; i < 4; ++i) {              // A: 1024 16B chunks
            int cid = tid + i * NTHREADS;
            int row = cid >> 3, seg = cid & 7;
            const __half* src = gA + (size_t)row * K_DIM + seg * 8;
            uint32_t dst = a_base + row * 128 + ((seg ^ (row & 7)) << 4);
            asm volatile("cp.async.cg.shared.global [%0], [%1], 16;\n"
                         :: "r"(dst), "l"(src));
        }
#pragma unroll
        for (int i = 0; i < 4; ++i) {              // B: 1024 16B chunks
            int cid = tid + i * NTHREADS;
            int row = cid >> 3, seg = cid & 7;
            const __half* src = gB + (size_t)row * K_DIM + seg * 8;
            uint32_t dst = b_base + row * 128 + ((seg ^ (row & 7)) << 4);
            asm volatile("cp.async.cg.shared.global [%0], [%1], 16;\n"
                         :: "r"(dst), "l"(src));
        }
    };

    // ---- ldmatrix lane addressing -----------------------------------------
    // A (no trans), x4 -> (m0-7,klo),(m8-15,klo),(m0-7,khi),(m8-15,khi)
    const int a_g  = lane >> 3;
    const int a_row_in = (lane & 7) + (a_g & 1) * 8;
    const int a_hi = a_g >> 1;                 // +8 halves in k
    // B (no trans; smem [n][k] k-contiguous = mma B layout),
    // x4 -> (n0-7,klo),(n0-7,khi),(n8-15,klo),(n8-15,khi)
    const int b_row_in = (lane & 7) + ((a_g >> 1) & 1) * 8;
    const int b_hi = a_g & 1;
    const int sxor = lane & 7;

    uint32_t a_row_off[4];
#pragma unroll
    for (int mi = 0; mi < 4; ++mi)
        a_row_off[mi] = (uint32_t)(warp_m + mi * 16 + a_row_in) * 128;
    uint32_t b_row_off[2];
#pragma unroll
    for (int nj = 0; nj < 2; ++nj)
        b_row_off[nj] = (uint32_t)(warp_n + nj * 16 + b_row_in) * 128;

    float acc[4][4][4];
#pragma unroll
    for (int mi = 0; mi < 4; ++mi)
#pragma unroll
        for (int nk = 0; nk < 4; ++nk)
#pragma unroll
            for (int r = 0; r < 4; ++r) acc[mi][nk][r] = 0.0f;

    // ---- one k16 compute step ---------------------------------------------
    auto compute_ks = [&](uint32_t a_base, uint32_t b_base, int ks) {
        uint32_t af[4][4];
        uint32_t bf[2][4];
#pragma unroll
        for (int mi = 0; mi < 4; ++mi) {
            uint32_t addr = a_base + a_row_off[mi]
                          + ((uint32_t)((ks * 2 + a_hi) ^ sxor) << 4);
            asm volatile(
                "ldmatrix.sync.aligned.m8n8.x4.shared.b16 {%0,%1,%2,%3}, [%4];\n"
                : "=r"(af[mi][0]), "=r"(af[mi][1]),
                  "=r"(af[mi][2]), "=r"(af[mi][3])
                : "r"(addr));
        }
#pragma unroll
        for (int nj = 0; nj < 2; ++nj) {
            uint32_t addr = b_base + b_row_off[nj]
                          + ((uint32_t)((ks * 2 + b_hi) ^ sxor) << 4);
            asm volatile(
                "ldmatrix.sync.aligned.m8n8.x4.shared.b16 {%0,%1,%2,%3}, [%4];\n"
                : "=r"(bf[nj][0]), "=r"(bf[nj][1]),
                  "=r"(bf[nj][2]), "=r"(bf[nj][3])
                : "r"(addr));
        }
#pragma unroll
        for (int mi = 0; mi < 4; ++mi) {
#pragma unroll
            for (int nk = 0; nk < 4; ++nk) {
                const int nj = nk >> 1;
                const int sub = (nk & 1) * 2;
                asm volatile(
                    "mma.sync.aligned.m16n8k16.row.col.f32.f16.f16.f32 "
                    "{%0,%1,%2,%3}, {%4,%5,%6,%7}, {%8,%9}, {%0,%1,%2,%3};\n"
                    : "+f"(acc[mi][nk][0]), "+f"(acc[mi][nk][1]),
                      "+f"(acc[mi][nk][2]), "+f"(acc[mi][nk][3])
                    : "r"(af[mi][0]), "r"(af[mi][1]),
                      "r"(af[mi][2]), "r"(af[mi][3]),
                      "r"(bf[nj][sub]), "r"(bf[nj][sub + 1]));
            }
        }
    };

    // ---- prologue: preload 2 stages ---------------------------------------
#pragma unroll
    for (int s = 0; s < STAGES - 1; ++s) {
        load_stage(s, s);
        asm volatile("cp.async.commit_group;\n");
    }

    // ---- mainloop ----------------------------------------------------------
    int stage = 0;
    for (int kt = 0; kt < KTILES; ++kt) {
        asm volatile("cp.async.wait_group %0;\n" :: "n"(STAGES - 2));
        __syncthreads();

        const int ld = kt + STAGES - 1;
        int lds = stage + (STAGES - 1);
        if (lds >= STAGES) lds -= STAGES;

        const uint32_t a_base = smem_u32 + stage * STAGE_BYTES;
        const uint32_t b_base = a_base + A_STAGE_BYTES;
        if (++stage == STAGES) stage = 0;

        // ks=0 first: the barrier-exit window issues only ldmatrix,
        // then the load burst goes out (commit immediately -> same
        // group accounting as R8), then the remaining 3 k-steps.
        compute_ks(a_base, b_base, 0);

        if (ld < KTILES) load_stage(lds, ld);
        asm volatile("cp.async.commit_group;\n");

        compute_ks(a_base, b_base, 1);
        compute_ks(a_base, b_base, 2);
        compute_ks(a_base, b_base, 3);
    }

    // ---- epilogue: bias + fp32 store --------------------------------------
    float bcol[4][2];
#pragma unroll
    for (int nk = 0; nk < 4; ++nk) {
        const int c = n0 + warp_n + nk * 8 + (lane & 3) * 2;
        bcol[nk][0] = bias[c];
        bcol[nk][1] = bias[c + 1];
    }
#pragma unroll
    for (int mi = 0; mi < 4; ++mi) {
        const int r0 = m0 + warp_m + mi * 16 + (lane >> 2);
#pragma unroll
        for (int nk = 0; nk < 4; ++nk) {
            const int c = n0 + warp_n + nk * 8 + (lane & 3) * 2;
            float2 v;
            v.x = acc[mi][nk][0] + bcol[nk][0];
            v.y = acc[mi][nk][1] + bcol[nk][1];
            *reinterpret_cast<float2*>(&out[(size_t)r0 * N_DIM + c]) = v;
            v.x = acc[mi][nk][2] + bcol[nk][0];
            v.y = acc[mi][nk][3] + bcol[nk][1];
            *reinterpret_cast<float2*>(&out[(size_t)(r0 + 8) * N_DIM + c]) = v;
        }
    }
}

// ---------------------------------------------------------------------------
// Launch
// ---------------------------------------------------------------------------

extern "C" void kernel_launch(void* const* d_in, const int* in_sizes, int n_in,
                              void* d_out, int out_size) {
    const float* x    = (const float*)d_in[0];
    const float* w    = (const float*)d_in[1];
    const float* bias = (const float*)d_in[2];
    float* out        = (float*)d_out;

    convert_both_kernel<<<3072, 256>>>(x, w);

    cudaFuncSetAttribute(binlinear_gemm_kernel,
                         cudaFuncAttributeMaxDynamicSharedMemorySize,
                         SMEM_BYTES);

    dim3 grid(N_DIM / BN, M_DIM / BM);   // (32, 64)
    binlinear_gemm_kernel<<<grid, NTHREADS, SMEM_BYTES>>>(bias, out);
}